// round 2
// baseline (speedup 1.0000x reference)
#include <cuda_runtime.h>
#include <cuda_fp16.h>
#include <cstdint>

#define NN      16384
#define DIMF    64
#define MT      128                 // output rows per CTA
#define KC      64                  // K elements per pipeline chunk
#define NC      (NN / KC)           // 256 chunks
#define THREADS 256
#define A_BYTES (MT * KC * 2)       // 16384  (fp16 A tile, 128 rows x 128B)
#define B_BYTES (DIMF * KC * 2)     // 8192   (fp16 B tile, 64 rows x 128B)
#define B_OFF   A_BYTES
#define STAGE_BYTES (A_BYTES + B_BYTES)   // 24576
#define DYN_SMEM (2 * STAGE_BYTES)        // 49152

// transposed x in fp16: g_xT[d][j] = (half)x[j][d]
__device__ __half g_xT[DIMF * NN];

// ---------------- helpers ----------------
__device__ __forceinline__ uint32_t smem_u32(const void* p) {
    uint32_t a;
    asm("{ .reg .u64 t; cvta.to.shared.u64 t, %1; cvt.u32.u64 %0, t; }"
        : "=r"(a) : "l"(p));
    return a;
}

__device__ __forceinline__ void ldmx4(uint32_t r[4], uint32_t addr) {
    asm volatile("ldmatrix.sync.aligned.m8n8.x4.shared.b16 {%0,%1,%2,%3}, [%4];"
                 : "=r"(r[0]), "=r"(r[1]), "=r"(r[2]), "=r"(r[3]) : "r"(addr));
}

__device__ __forceinline__ void mma16816(float* c, const uint32_t a[4],
                                         uint32_t b0, uint32_t b1) {
    asm volatile(
        "mma.sync.aligned.m16n8k16.row.col.f32.f16.f16.f32 "
        "{%0,%1,%2,%3}, {%4,%5,%6,%7}, {%8,%9}, {%0,%1,%2,%3};"
        : "+f"(c[0]), "+f"(c[1]), "+f"(c[2]), "+f"(c[3])
        : "r"(a[0]), "r"(a[1]), "r"(a[2]), "r"(a[3]), "r"(b0), "r"(b1));
}

__device__ __forceinline__ void cpa16(uint32_t dst, const void* src) {
    asm volatile("cp.async.cg.shared.global [%0], [%1], 16;"
                 :: "r"(dst), "l"(src) : "memory");
}

// ---------------- pre-pass: x -> transposed fp16 plane ----------------
__global__ void prep_x(const float* __restrict__ x) {
    int id = blockIdx.x * blockDim.x + threadIdx.x;   // 0 .. 64*16384-1
    int d = id >> 14;
    int j = id & (NN - 1);
    g_xT[(size_t)d * NN + j] = __float2half(x[(size_t)j * DIMF + d]);
}

// ---------------- main fused convert + mma.sync GEMM ----------------
__global__ void __launch_bounds__(THREADS, 1)
gp_mma(const float* __restrict__ x, const int* __restrict__ adj,
       float* __restrict__ out) {
    extern __shared__ __align__(1024) char smem[];
    const uint32_t sb = smem_u32(smem);
    const int tid = threadIdx.x;
    const int lane = tid & 31;
    const int wid = tid >> 5;
    const int m0 = blockIdx.x * MT;

    // ---- producer addressing ----
    // A: 128 rows x 64 int32 per chunk; 2 threads/row, 32 consecutive int32 each
    const int rowA = tid >> 1;
    const int kwA = (tid & 1) * 32;
    const int* aptr = adj + (size_t)(m0 + rowA) * NN + kwA;
    uint32_t asw[4];
    {
        uint32_t o0 = (uint32_t)rowA * 128 + (uint32_t)(tid & 1) * 64;
#pragma unroll
        for (int i = 0; i < 4; i++) {
            uint32_t o = o0 + i * 16;
            asw[i] = o ^ ((o >> 3) & 0x70);
        }
    }
    // B: 64 rows (n=d) x 64 halves per chunk; 4 threads/row, 16 halves each
    const int rowB = tid >> 2;
    const int khB = (tid & 3) * 16;
    const __half* bptr = g_xT + (size_t)rowB * NN + khB;
    uint32_t bsw[2];
    {
        uint32_t o0 = (uint32_t)rowB * 128 + (uint32_t)(tid & 3) * 32;
#pragma unroll
        for (int i = 0; i < 2; i++) {
            uint32_t o = o0 + i * 16;
            bsw[i] = (o ^ ((o >> 3) & 0x70)) + B_OFF;
        }
    }

    // ---- consumer addressing (swizzled, ktile advances by XOR of kt<<5) ----
    const int wm = wid >> 1;   // 0..3 : 32-row slice
    const int wn = wid & 1;    // 0..1 : 32-col slice
    uint32_t aAddr[2];
#pragma unroll
    for (int mt = 0; mt < 2; mt++) {
        uint32_t row = (uint32_t)(wm * 32 + mt * 16 + (lane & 15));
        uint32_t o = row * 128 + (((uint32_t)lane >> 4) << 4);
        aAddr[mt] = o ^ ((o >> 3) & 0x70);
    }
    uint32_t bAddr[2];
#pragma unroll
    for (int p = 0; p < 2; p++) {
        uint32_t n = (uint32_t)(wn * 32 + p * 16 + (lane & 7) + ((lane >> 4) & 1) * 8);
        uint32_t o = n * 128 + ((((uint32_t)lane >> 3) & 1) << 4);
        bAddr[p] = (o ^ ((o >> 3) & 0x70)) + B_OFF;
    }

    // ---- prologue: chunk 0 loads ----
    uint4 ra[8];
#pragma unroll
    for (int i = 0; i < 8; i++) ra[i] = *(const uint4*)(aptr + i * 4);
    cpa16(sb + bsw[0], bptr);
    cpa16(sb + bsw[1], bptr + 8);
    asm volatile("cp.async.commit_group;" ::: "memory");

    float acc[32];
#pragma unroll
    for (int i = 0; i < 32; i++) acc[i] = 0.f;

    for (int c = 0; c < NC; c++) {
        const uint32_t st = (uint32_t)(c & 1) * STAGE_BYTES;
        __syncthreads();   // buffer (c&1) free (consumed at c-2)

        // pack int32 0/1 -> fp16x2 (PRMT low bytes, * fp16(1.0)=0x3C00) + STS
#pragma unroll
        for (int q = 0; q < 4; q++) {
            uint4 w;
            w.x = __byte_perm(ra[2 * q].x, ra[2 * q].y, 0x5410) * 0x3C00u;
            w.y = __byte_perm(ra[2 * q].z, ra[2 * q].w, 0x5410) * 0x3C00u;
            w.z = __byte_perm(ra[2 * q + 1].x, ra[2 * q + 1].y, 0x5410) * 0x3C00u;
            w.w = __byte_perm(ra[2 * q + 1].z, ra[2 * q + 1].w, 0x5410) * 0x3C00u;
            *(uint4*)(smem + st + asw[q]) = w;
        }
        asm volatile("cp.async.wait_group 0;" ::: "memory");  // B(c) landed
        __syncthreads();   // stage c visible to all

        if (c + 1 < NC) {
            // prefetch chunk c+1 while computing chunk c
            const int* ap = aptr + (c + 1) * KC;
#pragma unroll
            for (int i = 0; i < 8; i++) ra[i] = *(const uint4*)(ap + i * 4);
            const __half* bp = bptr + (c + 1) * KC;
            const uint32_t st2 = (uint32_t)((c + 1) & 1) * STAGE_BYTES;
            cpa16(sb + st2 + bsw[0], bp);
            cpa16(sb + st2 + bsw[1], bp + 8);
            asm volatile("cp.async.commit_group;" ::: "memory");
        }

        // ---- compute: 4 k16 steps x (2 mtiles x 4 ntiles) mma ----
        const uint32_t base = sb + st;
#pragma unroll
        for (int kt = 0; kt < 4; kt++) {
            const uint32_t kx = (uint32_t)kt << 5;
            uint32_t a0[4], a1[4], b0[4], b1[4];
            ldmx4(a0, base + (aAddr[0] ^ kx));
            ldmx4(a1, base + (aAddr[1] ^ kx));
            ldmx4(b0, base + (bAddr[0] ^ kx));
            ldmx4(b1, base + (bAddr[1] ^ kx));
#pragma unroll
            for (int mt = 0; mt < 2; mt++) {
                const uint32_t* A = mt ? a1 : a0;
                float* am = acc + mt * 16;
                mma16816(am + 0, A, b0[0], b0[1]);   // n-tile 0 (cols +0..7)
                mma16816(am + 4, A, b0[2], b0[3]);   // n-tile 1 (cols +8..15)
                mma16816(am + 8, A, b1[0], b1[1]);   // n-tile 2 (cols +16..23)
                mma16816(am + 12, A, b1[2], b1[3]);  // n-tile 3 (cols +24..31)
            }
        }
    }

    // ---- epilogue: out = acc + x (fp32 exact self term) ----
#pragma unroll
    for (int mt = 0; mt < 2; mt++) {
        const int r0 = m0 + wm * 32 + mt * 16 + (lane >> 2);
#pragma unroll
        for (int nt = 0; nt < 4; nt++) {
            const int col = wn * 32 + nt * 8 + (lane & 3) * 2;
            const float* ap = acc + mt * 16 + nt * 4;
            float2 xv0 = *(const float2*)(x + (size_t)r0 * DIMF + col);
            float2 o0 = make_float2(ap[0] + xv0.x, ap[1] + xv0.y);
            *(float2*)(out + (size_t)r0 * DIMF + col) = o0;
            float2 xv1 = *(const float2*)(x + (size_t)(r0 + 8) * DIMF + col);
            float2 o1 = make_float2(ap[2] + xv1.x, ap[3] + xv1.y);
            *(float2*)(out + (size_t)(r0 + 8) * DIMF + col) = o1;
        }
    }
}

extern "C" void kernel_launch(void* const* d_in, const int* in_sizes, int n_in,
                              void* d_out, int out_size) {
    const float* x = (const float*)d_in[0];
    const int* adj = (const int*)d_in[1];
    float* out = (float*)d_out;

    prep_x<<<(NN * DIMF) / 256, 256>>>(x);

    cudaFuncSetAttribute(gp_mma, cudaFuncAttributeMaxDynamicSharedMemorySize,
                         DYN_SMEM);
    gp_mma<<<NN / MT, THREADS, DYN_SMEM>>>(x, adj, out);
}

// round 3
// speedup vs baseline: 1.1675x; 1.1675x over previous
#include <cuda_runtime.h>
#include <cuda_fp16.h>
#include <cstdint>

#define NN      16384
#define DIMF    64
#define MT      128                   // output rows per CTA
#define KC      64                    // K elements per pipeline chunk
#define NC      (NN / KC)             // 256 chunks
#define THREADS 256
#define A_STAGE (MT * KC * 2)         // 16384 bytes (fp16 A tile)
#define B_STAGE (DIMF * KC * 2)       // 8192 bytes  (fp16 B tile)
#define B_BASE  (2 * A_STAGE)         // 32768
#define DYN_SMEM (B_BASE + 4 * B_STAGE)   // 65536

// transposed x in fp16: g_xT[d][j] = (half)x[j][d]
__device__ __half g_xT[DIMF * NN];

// ---------------- helpers ----------------
__device__ __forceinline__ uint32_t smem_u32(const void* p) {
    uint32_t a;
    asm("{ .reg .u64 t; cvta.to.shared.u64 t, %1; cvt.u32.u64 %0, t; }"
        : "=r"(a) : "l"(p));
    return a;
}

__device__ __forceinline__ void ldmx4(uint32_t r[4], uint32_t addr) {
    asm volatile("ldmatrix.sync.aligned.m8n8.x4.shared.b16 {%0,%1,%2,%3}, [%4];"
                 : "=r"(r[0]), "=r"(r[1]), "=r"(r[2]), "=r"(r[3]) : "r"(addr));
}

__device__ __forceinline__ void mma16816(float* c, const uint32_t a[4],
                                         uint32_t b0, uint32_t b1) {
    asm volatile(
        "mma.sync.aligned.m16n8k16.row.col.f32.f16.f16.f32 "
        "{%0,%1,%2,%3}, {%4,%5,%6,%7}, {%8,%9}, {%0,%1,%2,%3};"
        : "+f"(c[0]), "+f"(c[1]), "+f"(c[2]), "+f"(c[3])
        : "r"(a[0]), "r"(a[1]), "r"(a[2]), "r"(a[3]), "r"(b0), "r"(b1));
}

__device__ __forceinline__ void cpa16(uint32_t dst, const void* src) {
    asm volatile("cp.async.cg.shared.global [%0], [%1], 16;"
                 :: "r"(dst), "l"(src) : "memory");
}

// ---------------- pre-pass: x -> transposed fp16 plane ----------------
__global__ void prep_x(const float* __restrict__ x) {
    int id = blockIdx.x * blockDim.x + threadIdx.x;   // 0 .. 64*16384-1
    int d = id >> 14;
    int j = id & (NN - 1);
    g_xT[(size_t)d * NN + j] = __float2half(x[(size_t)j * DIMF + d]);
}

// ---------------- main fused convert + mma.sync GEMM ----------------
__global__ void __launch_bounds__(THREADS, 1)
gp_mma(const float* __restrict__ x, const int* __restrict__ adj,
       float* __restrict__ out) {
    extern __shared__ __align__(1024) char smem[];
    const uint32_t sb = smem_u32(smem);
    const int tid = threadIdx.x;
    const int lane = tid & 31;
    const int wid = tid >> 5;
    const int m0 = blockIdx.x * MT;

    // ---- producer A addressing: COALESCED ----
    // 16 lanes per row-chunk segment (16 x 16B = full 256B); warp = 2 rows.
    const int rsub = tid >> 4;        // 0..15
    const int kq = tid & 15;          // 0..15 (x 4 int32 = 16B)
    const int* aptr = adj + (size_t)(m0 + rsub) * NN + kq * 4;
    uint32_t asw[8];
#pragma unroll
    for (int i = 0; i < 8; i++) {
        uint32_t row = (uint32_t)(rsub + 16 * i);
        uint32_t o = row * 128 + (uint32_t)kq * 8;
        asw[i] = o ^ ((o >> 3) & 0x70);
    }

    // ---- producer B addressing: 4 threads/row, 16 halves (32B) each ----
    const int rowB = tid >> 2;
    const __half* bptr = g_xT + (size_t)rowB * NN + (tid & 3) * 16;
    uint32_t bsw[2];
    {
        uint32_t o0 = (uint32_t)rowB * 128 + (uint32_t)(tid & 3) * 32;
#pragma unroll
        for (int i = 0; i < 2; i++) {
            uint32_t o = o0 + i * 16;
            bsw[i] = o ^ ((o >> 3) & 0x70);
        }
    }

    // ---- consumer addressing (swizzled; k-tile advances by XOR of kt<<5) ----
    const int wm = wid >> 1;   // 0..3 : 32-row slice
    const int wn = wid & 1;    // 0..1 : 32-col slice
    uint32_t aAddr[2];
#pragma unroll
    for (int mt = 0; mt < 2; mt++) {
        uint32_t row = (uint32_t)(wm * 32 + mt * 16 + (lane & 15));
        uint32_t o = row * 128 + (((uint32_t)lane >> 4) << 4);
        aAddr[mt] = o ^ ((o >> 3) & 0x70);
    }
    uint32_t bAddr[2];
#pragma unroll
    for (int p = 0; p < 2; p++) {
        uint32_t n = (uint32_t)(wn * 32 + p * 16 + (lane & 7) + ((lane >> 4) & 1) * 8);
        uint32_t o = n * 128 + ((((uint32_t)lane >> 3) & 1) << 4);
        bAddr[p] = o ^ ((o >> 3) & 0x70);
    }

    // ---- prologue: A chunks 0,1 into regs; B chunks 0,1 via cp.async ----
    uint4 ra[2][8];
#pragma unroll
    for (int i = 0; i < 8; i++)
        ra[0][i] = *(const uint4*)(aptr + (size_t)i * (16 * NN));
    cpa16(sb + B_BASE + bsw[0], bptr);
    cpa16(sb + B_BASE + bsw[1], bptr + 8);
    asm volatile("cp.async.commit_group;" ::: "memory");
#pragma unroll
    for (int i = 0; i < 8; i++)
        ra[1][i] = *(const uint4*)(aptr + (size_t)i * (16 * NN) + KC);
    cpa16(sb + B_BASE + B_STAGE + bsw[0], bptr + KC);
    cpa16(sb + B_BASE + B_STAGE + bsw[1], bptr + KC + 8);
    asm volatile("cp.async.commit_group;" ::: "memory");

    float acc[32];
#pragma unroll
    for (int i = 0; i < 32; i++) acc[i] = 0.f;

    for (int c = 0; c < NC; c++) {
        const int pa = c & 1;
        const uint32_t aBase = sb + (uint32_t)pa * A_STAGE;
        const uint32_t bBase = sb + B_BASE + (uint32_t)(c & 3) * B_STAGE;

        __syncthreads();   // A stage pa free; B stage (c&3) free

        // convert + STS A(c): int32 0/1 -> fp16x2 (PRMT low bytes * 0x3C00)
#pragma unroll
        for (int i = 0; i < 8; i++) {
            uint2 w;
            w.x = __byte_perm(ra[pa][i].x, ra[pa][i].y, 0x5410) * 0x3C00u;
            w.y = __byte_perm(ra[pa][i].z, ra[pa][i].w, 0x5410) * 0x3C00u;
            *(uint2*)(smem + (uint32_t)pa * A_STAGE + asw[i]) = w;
        }

        // issue B(c+2) into stage (c+2)&3; ALWAYS commit (keeps group count exact)
        if (c + 2 < NC) {
            const __half* bp = bptr + (size_t)(c + 2) * KC;
            const uint32_t bd = sb + B_BASE + (uint32_t)((c + 2) & 3) * B_STAGE;
            cpa16(bd + bsw[0], bp);
            cpa16(bd + bsw[1], bp + 8);
        }
        asm volatile("cp.async.commit_group;" ::: "memory");
        // groups committed: 0..c+2 ; <=2 pending  =>  group c (B(c)) done
        asm volatile("cp.async.wait_group 2;" ::: "memory");
        __syncthreads();   // stage contents visible

        // prefetch A(c+2) into just-freed registers
        if (c + 2 < NC) {
            const int* ap = aptr + (size_t)(c + 2) * KC;
#pragma unroll
            for (int i = 0; i < 8; i++)
                ra[pa][i] = *(const uint4*)(ap + (size_t)i * (16 * NN));
        }

        // ---- compute: 4 k16 steps x (2 mtiles x 4 ntiles) mma ----
#pragma unroll
        for (int kt = 0; kt < 4; kt++) {
            const uint32_t kx = (uint32_t)kt << 5;
            uint32_t a0[4], a1[4], b0[4], b1[4];
            ldmx4(a0, aBase + (aAddr[0] ^ kx));
            ldmx4(a1, aBase + (aAddr[1] ^ kx));
            ldmx4(b0, bBase + (bAddr[0] ^ kx));
            ldmx4(b1, bBase + (bAddr[1] ^ kx));
#pragma unroll
            for (int mt = 0; mt < 2; mt++) {
                const uint32_t* A = mt ? a1 : a0;
                float* am = acc + mt * 16;
                mma16816(am + 0, A, b0[0], b0[1]);
                mma16816(am + 4, A, b0[2], b0[3]);
                mma16816(am + 8, A, b1[0], b1[1]);
                mma16816(am + 12, A, b1[2], b1[3]);
            }
        }
    }

    // ---- epilogue: out = acc + x (fp32 exact self term) ----
#pragma unroll
    for (int mt = 0; mt < 2; mt++) {
        const int r0 = m0 + wm * 32 + mt * 16 + (lane >> 2);
#pragma unroll
        for (int nt = 0; nt < 4; nt++) {
            const int col = wn * 32 + nt * 8 + (lane & 3) * 2;
            const float* ap = acc + mt * 16 + nt * 4;
            float2 xv0 = *(const float2*)(x + (size_t)r0 * DIMF + col);
            *(float2*)(out + (size_t)r0 * DIMF + col) =
                make_float2(ap[0] + xv0.x, ap[1] + xv0.y);
            float2 xv1 = *(const float2*)(x + (size_t)(r0 + 8) * DIMF + col);
            *(float2*)(out + (size_t)(r0 + 8) * DIMF + col) =
                make_float2(ap[2] + xv1.x, ap[3] + xv1.y);
        }
    }
}

extern "C" void kernel_launch(void* const* d_in, const int* in_sizes, int n_in,
                              void* d_out, int out_size) {
    const float* x = (const float*)d_in[0];
    const int* adj = (const int*)d_in[1];
    float* out = (float*)d_out;

    prep_x<<<(NN * DIMF) / 256, 256>>>(x);

    cudaFuncSetAttribute(gp_mma, cudaFuncAttributeMaxDynamicSharedMemorySize,
                         DYN_SMEM);
    gp_mma<<<NN / MT, THREADS, DYN_SMEM>>>(x, adj, out);
}

// round 4
// speedup vs baseline: 2.5452x; 2.1800x over previous
#include <cuda_runtime.h>
#include <cuda_fp16.h>
#include <cstdint>

#define NN      16384
#define DIMF    64
#define MT      128                   // output rows per CTA
#define KC      64                    // K elements per pipeline chunk
#define NC      (NN / KC)             // 256 chunks
#define THREADS 256
#define A_STAGE 32768                 // raw int32 A tile: 128 rows x 256B
#define B_STAGE 8192                  // fp16 B tile: 64 rows x 128B
#define B_BASE  (4 * A_STAGE)         // 131072
#define DYN_SMEM (B_BASE + 4 * B_STAGE)   // 163840

// transposed x in fp16: g_xT[d][j] = (half)x[j][d]
__device__ __half g_xT[DIMF * NN];

// ---------------- helpers ----------------
__device__ __forceinline__ uint32_t smem_u32(const void* p) {
    uint32_t a;
    asm("{ .reg .u64 t; cvta.to.shared.u64 t, %1; cvt.u32.u64 %0, t; }"
        : "=r"(a) : "l"(p));
    return a;
}

__device__ __forceinline__ void ldmx4(uint32_t r[4], uint32_t addr) {
    asm volatile("ldmatrix.sync.aligned.m8n8.x4.shared.b16 {%0,%1,%2,%3}, [%4];"
                 : "=r"(r[0]), "=r"(r[1]), "=r"(r[2]), "=r"(r[3]) : "r"(addr));
}

__device__ __forceinline__ void mma16816(float* c, const uint32_t a[4],
                                         uint32_t b0, uint32_t b1) {
    asm volatile(
        "mma.sync.aligned.m16n8k16.row.col.f32.f16.f16.f32 "
        "{%0,%1,%2,%3}, {%4,%5,%6,%7}, {%8,%9}, {%0,%1,%2,%3};"
        : "+f"(c[0]), "+f"(c[1]), "+f"(c[2]), "+f"(c[3])
        : "r"(a[0]), "r"(a[1]), "r"(a[2]), "r"(a[3]), "r"(b0), "r"(b1));
}

__device__ __forceinline__ void cpa16(uint32_t dst, const void* src) {
    asm volatile("cp.async.cg.shared.global [%0], [%1], 16;"
                 :: "r"(dst), "l"(src) : "memory");
}

// ---------------- pre-pass: x -> transposed fp16 plane ----------------
__global__ void prep_x(const float* __restrict__ x) {
    int id = blockIdx.x * blockDim.x + threadIdx.x;   // 0 .. 64*16384-1
    int d = id >> 14;
    int j = id & (NN - 1);
    g_xT[(size_t)d * NN + j] = __float2half(x[(size_t)j * DIMF + d]);
}

// ---------------- main fused convert + mma.sync GEMM ----------------
__global__ void __launch_bounds__(THREADS, 1)
gp_mma(const float* __restrict__ x, const int* __restrict__ adj,
       float* __restrict__ out) {
    extern __shared__ __align__(1024) char smem[];
    const uint32_t sb = smem_u32(smem);
    const int tid = threadIdx.x;
    const int lane = tid & 31;
    const int wid = tid >> 5;
    const int m0 = blockIdx.x * MT;

    // ---- producer A: cp.async of RAW int32, perfectly coalesced ----
    // thread = (rowp, gg): 16B granule gg of rows rowp+16i; granule swizzle
    // g' = g ^ ((row&3)<<1) makes consumer LDS.64 conflict-free.
    const int rowp = tid >> 4;          // 0..15
    const int gg = tid & 15;            // 0..15 (16B granules of a 256B row)
    const int* aps = adj + (size_t)(m0 + rowp) * NN + gg * 4;
    uint32_t adst[8];
#pragma unroll
    for (int i = 0; i < 8; i++) {
        uint32_t row = (uint32_t)(rowp + 16 * i);
        adst[i] = row * 256 + (((uint32_t)gg ^ ((row & 3u) << 1)) << 4);
    }

    // ---- producer B: 4 threads/row, 32B each ----
    const int rowB = tid >> 2;
    const __half* bptr = g_xT + (size_t)rowB * NN + (tid & 3) * 16;
    uint32_t bsw[2];
    {
        uint32_t o0 = (uint32_t)rowB * 128 + (uint32_t)(tid & 3) * 32;
#pragma unroll
        for (int i = 0; i < 2; i++) {
            uint32_t o = o0 + i * 16;
            bsw[i] = o ^ ((o >> 3) & 0x70);
        }
    }

    // ---- consumer addressing ----
    const int wm = wid >> 1;   // 0..3 : 32-row slice
    const int wn = wid & 1;    // 0..1 : 32-col slice
    // A: direct fragment assembly from raw int32.
    // frag reg j of m-tile mt at k-step kt reads 8B at:
    //   row = wm*32 + mt*16 + (lane>>2) + (j&1)*8
    //   unit = kt*8 + (lane&3) + (j>>1)*4 ;  unit ^= ((row&3)<<2)
    const uint32_t xr = (((uint32_t)lane >> 2) & 3u) << 2;
    uint32_t rowb[4];   // [mt*2 + (j&1)] -> row*256
#pragma unroll
    for (int mt = 0; mt < 2; mt++)
#pragma unroll
        for (int jl = 0; jl < 2; jl++)
            rowb[mt * 2 + jl] =
                (uint32_t)(wm * 32 + mt * 16 + (lane >> 2) + jl * 8) * 256;
    uint32_t kuo[8];    // [kt*2 + (j>>1)] -> swizzled unit byte offset
#pragma unroll
    for (int kt = 0; kt < 4; kt++)
#pragma unroll
        for (int jh = 0; jh < 2; jh++)
            kuo[kt * 2 + jh] =
                (((uint32_t)(kt * 8 + (lane & 3) + jh * 4) ^ xr) << 3);

    // B: ldmatrix addressing (swizzled; k-tile advances by XOR of kt<<5)
    uint32_t bAddr[2];
#pragma unroll
    for (int p = 0; p < 2; p++) {
        uint32_t n = (uint32_t)(wn * 32 + p * 16 + (lane & 7) + ((lane >> 4) & 1) * 8);
        uint32_t o = n * 128 + ((((uint32_t)lane >> 3) & 1) << 4);
        bAddr[p] = o ^ ((o >> 3) & 0x70);
    }

    // ---- prologue: chunks 0,1,2 in flight ----
#pragma unroll
    for (int pre = 0; pre < 3; pre++) {
        const uint32_t ad = sb + (uint32_t)(pre & 3) * A_STAGE;
#pragma unroll
        for (int i = 0; i < 8; i++)
            cpa16(ad + adst[i], aps + (size_t)i * (16 * NN) + pre * KC);
        const uint32_t bd = sb + B_BASE + (uint32_t)(pre & 3) * B_STAGE;
        cpa16(bd + bsw[0], bptr + pre * KC);
        cpa16(bd + bsw[1], bptr + pre * KC + 8);
        asm volatile("cp.async.commit_group;" ::: "memory");
    }

    float acc[32];
#pragma unroll
    for (int i = 0; i < 32; i++) acc[i] = 0.f;

    for (int c = 0; c < NC; c++) {
        // own groups: <=2 pending -> group c complete
        asm volatile("cp.async.wait_group 2;" ::: "memory");
        __syncthreads();   // group-c data visible to all; WAR for stage (c+3)&3

        // issue chunk c+3 (stage (c+3)&3 == (c-1)&3, last read at iter c-1)
        if (c + 3 < NC) {
            const uint32_t ad = sb + (uint32_t)((c + 3) & 3) * A_STAGE;
#pragma unroll
            for (int i = 0; i < 8; i++)
                cpa16(ad + adst[i], aps + (size_t)i * (16 * NN) + (c + 3) * KC);
            const uint32_t bd = sb + B_BASE + (uint32_t)((c + 3) & 3) * B_STAGE;
            cpa16(bd + bsw[0], bptr + (size_t)(c + 3) * KC);
            cpa16(bd + bsw[1], bptr + (size_t)(c + 3) * KC + 8);
        }
        asm volatile("cp.async.commit_group;" ::: "memory");

        const uint32_t aOff = (uint32_t)(c & 3) * A_STAGE;
        const uint32_t bBase = sb + B_BASE + (uint32_t)(c & 3) * B_STAGE;

        // ---- compute chunk c: 4 k16 steps ----
#pragma unroll
        for (int kt = 0; kt < 4; kt++) {
            const uint32_t kx = (uint32_t)kt << 5;
            uint32_t b0[4], b1[4];
            ldmx4(b0, bBase + (bAddr[0] ^ kx));
            ldmx4(b1, bBase + (bAddr[1] ^ kx));
#pragma unroll
            for (int mt = 0; mt < 2; mt++) {
                uint32_t A[4];
#pragma unroll
                for (int j = 0; j < 4; j++) {
                    const uint2 v = *reinterpret_cast<const uint2*>(
                        smem + aOff + rowb[mt * 2 + (j & 1)] + kuo[kt * 2 + (j >> 1)]);
                    A[j] = __byte_perm(v.x, v.y, 0x5410) * 0x3C00u;
                }
                float* am = acc + mt * 16;
                mma16816(am + 0, A, b0[0], b0[1]);
                mma16816(am + 4, A, b0[2], b0[3]);
                mma16816(am + 8, A, b1[0], b1[1]);
                mma16816(am + 12, A, b1[2], b1[3]);
            }
        }
    }

    // ---- epilogue: out = acc + x (fp32 exact self term) ----
#pragma unroll
    for (int mt = 0; mt < 2; mt++) {
        const int r0 = m0 + wm * 32 + mt * 16 + (lane >> 2);
#pragma unroll
        for (int nt = 0; nt < 4; nt++) {
            const int col = wn * 32 + nt * 8 + (lane & 3) * 2;
            const float* ap = acc + mt * 16 + nt * 4;
            float2 xv0 = *(const float2*)(x + (size_t)r0 * DIMF + col);
            *(float2*)(out + (size_t)r0 * DIMF + col) =
                make_float2(ap[0] + xv0.x, ap[1] + xv0.y);
            float2 xv1 = *(const float2*)(x + (size_t)(r0 + 8) * DIMF + col);
            *(float2*)(out + (size_t)(r0 + 8) * DIMF + col) =
                make_float2(ap[2] + xv1.x, ap[3] + xv1.y);
        }
    }
}

extern "C" void kernel_launch(void* const* d_in, const int* in_sizes, int n_in,
                              void* d_out, int out_size) {
    const float* x = (const float*)d_in[0];
    const int* adj = (const int*)d_in[1];
    float* out = (float*)d_out;

    prep_x<<<(NN * DIMF) / 256, 256>>>(x);

    cudaFuncSetAttribute(gp_mma, cudaFuncAttributeMaxDynamicSharedMemorySize,
                         DYN_SMEM);
    gp_mma<<<NN / MT, THREADS, DYN_SMEM>>>(x, adj, out);
}

// round 5
// speedup vs baseline: 2.6180x; 1.0286x over previous
#include <cuda_runtime.h>
#include <cuda_fp16.h>
#include <cstdint>

#define NN      16384
#define DIMF    64
#define MT      64                    // output rows per CTA
#define KC      64                    // K elements per pipeline chunk
#define NC      (NN / KC)             // 256 chunks
#define THREADS 128
#define A_STAGE 16384                 // raw int32 A tile: 64 rows x 256B
#define B_STAGE 8192                  // fp16 B tile: 64 rows x 128B
#define B_BASE  (4 * A_STAGE)         // 65536
#define DYN_SMEM (B_BASE + 4 * B_STAGE)   // 98304

// transposed x in fp16: g_xT[d][j] = (half)x[j][d]
__device__ __half g_xT[DIMF * NN];

// ---------------- helpers ----------------
__device__ __forceinline__ uint32_t smem_u32(const void* p) {
    uint32_t a;
    asm("{ .reg .u64 t; cvta.to.shared.u64 t, %1; cvt.u32.u64 %0, t; }"
        : "=r"(a) : "l"(p));
    return a;
}

__device__ __forceinline__ void ldmx4(uint32_t r[4], uint32_t addr) {
    asm volatile("ldmatrix.sync.aligned.m8n8.x4.shared.b16 {%0,%1,%2,%3}, [%4];"
                 : "=r"(r[0]), "=r"(r[1]), "=r"(r[2]), "=r"(r[3]) : "r"(addr));
}

__device__ __forceinline__ void mma16816(float* c, const uint32_t a[4],
                                         uint32_t b0, uint32_t b1) {
    asm volatile(
        "mma.sync.aligned.m16n8k16.row.col.f32.f16.f16.f32 "
        "{%0,%1,%2,%3}, {%4,%5,%6,%7}, {%8,%9}, {%0,%1,%2,%3};"
        : "+f"(c[0]), "+f"(c[1]), "+f"(c[2]), "+f"(c[3])
        : "r"(a[0]), "r"(a[1]), "r"(a[2]), "r"(a[3]), "r"(b0), "r"(b1));
}

__device__ __forceinline__ void cpa16(uint32_t dst, const void* src) {
    asm volatile("cp.async.cg.shared.global [%0], [%1], 16;"
                 :: "r"(dst), "l"(src) : "memory");
}

// ---------------- pre-pass: x -> transposed fp16 plane ----------------
__global__ void prep_x(const float* __restrict__ x) {
    int id = blockIdx.x * blockDim.x + threadIdx.x;   // 0 .. 64*16384-1
    int d = id >> 14;
    int j = id & (NN - 1);
    g_xT[(size_t)d * NN + j] = __float2half(x[(size_t)j * DIMF + d]);
}

// ---------------- main fused convert + mma.sync GEMM ----------------
__global__ void __launch_bounds__(THREADS, 2)
gp_mma(const float* __restrict__ x, const int* __restrict__ adj,
       float* __restrict__ out) {
    extern __shared__ __align__(1024) char smem[];
    const uint32_t sb = smem_u32(smem);
    const int tid = threadIdx.x;
    const int lane = tid & 31;
    const int wid = tid >> 5;          // 0..3
    const int m0 = blockIdx.x * MT;

    // ---- producer A: cp.async of RAW int32, coalesced ----
    // thread = (rowp, gg): 16B granule gg of rows rowp+8i; granule swizzle
    // g' = g ^ ((row&3)<<1) keeps consumer LDS.64 conflict-free.
    const int rowp = tid >> 4;          // 0..7
    const int gg = tid & 15;            // 0..15 (16B granules of a 256B row)
    const int* aps = adj + (size_t)(m0 + rowp) * NN + gg * 4;
    uint32_t adst[8];
#pragma unroll
    for (int i = 0; i < 8; i++) {
        uint32_t row = (uint32_t)(rowp + 8 * i);
        adst[i] = row * 256 + (((uint32_t)gg ^ ((row & 3u) << 1)) << 4);
    }

    // ---- producer B: 2 threads/row, 64B (4 granules) each ----
    const int rowB = tid >> 1;          // 0..63
    const int hb = tid & 1;             // 0..1 (64B half of 128B row)
    const __half* bptr = g_xT + (size_t)rowB * NN + hb * 32;
    uint32_t bsw[4];
    {
        uint32_t o0 = (uint32_t)rowB * 128 + (uint32_t)hb * 64;
#pragma unroll
        for (int i = 0; i < 4; i++) {
            uint32_t o = o0 + i * 16;
            bsw[i] = o ^ ((o >> 3) & 0x70);
        }
    }

    // ---- consumer addressing ----
    const int wm = wid >> 1;   // 0..1 : 32-row slice
    const int wn = wid & 1;    // 0..1 : 32-col slice
    // A: direct fragment assembly from raw int32 in smem.
    const uint32_t xr = (((uint32_t)lane >> 2) & 3u) << 2;
    uint32_t rowb[4];   // [mt*2 + (j&1)] -> row*256
#pragma unroll
    for (int mt = 0; mt < 2; mt++)
#pragma unroll
        for (int jl = 0; jl < 2; jl++)
            rowb[mt * 2 + jl] =
                (uint32_t)(wm * 32 + mt * 16 + (lane >> 2) + jl * 8) * 256;
    uint32_t kuo[8];    // [kt*2 + (j>>1)] -> swizzled unit byte offset
#pragma unroll
    for (int kt = 0; kt < 4; kt++)
#pragma unroll
        for (int jh = 0; jh < 2; jh++)
            kuo[kt * 2 + jh] =
                (((uint32_t)(kt * 8 + (lane & 3) + jh * 4) ^ xr) << 3);

    // B: ldmatrix addressing (swizzled; k-tile advances by XOR of kt<<5)
    uint32_t bAddr[2];
#pragma unroll
    for (int p = 0; p < 2; p++) {
        uint32_t n = (uint32_t)(wn * 32 + p * 16 + (lane & 7) + ((lane >> 4) & 1) * 8);
        uint32_t o = n * 128 + ((((uint32_t)lane >> 3) & 1) << 4);
        bAddr[p] = o ^ ((o >> 3) & 0x70);
    }

    // ---- prologue: chunks 0,1,2 in flight ----
#pragma unroll
    for (int pre = 0; pre < 3; pre++) {
        const uint32_t ad = sb + (uint32_t)(pre & 3) * A_STAGE;
#pragma unroll
        for (int i = 0; i < 8; i++)
            cpa16(ad + adst[i], aps + (size_t)i * (8 * NN) + pre * KC);
        const uint32_t bd = sb + B_BASE + (uint32_t)(pre & 3) * B_STAGE;
#pragma unroll
        for (int i = 0; i < 4; i++)
            cpa16(bd + bsw[i], bptr + pre * KC + i * 8);
        asm volatile("cp.async.commit_group;" ::: "memory");
    }

    float acc[32];
#pragma unroll
    for (int i = 0; i < 32; i++) acc[i] = 0.f;

    for (int c = 0; c < NC; c++) {
        // own groups: <=2 pending -> group c complete
        asm volatile("cp.async.wait_group 2;" ::: "memory");
        __syncthreads();   // group-c data visible to all; WAR for stage (c+3)&3

        // issue chunk c+3 into stage (c+3)&3 (== (c-1)&3, last read at c-1)
        if (c + 3 < NC) {
            const uint32_t ad = sb + (uint32_t)((c + 3) & 3) * A_STAGE;
#pragma unroll
            for (int i = 0; i < 8; i++)
                cpa16(ad + adst[i], aps + (size_t)i * (8 * NN) + (c + 3) * KC);
            const uint32_t bd = sb + B_BASE + (uint32_t)((c + 3) & 3) * B_STAGE;
#pragma unroll
            for (int i = 0; i < 4; i++)
                cpa16(bd + bsw[i], bptr + (size_t)(c + 3) * KC + i * 8);
        }
        asm volatile("cp.async.commit_group;" ::: "memory");

        const uint32_t aOff = (uint32_t)(c & 3) * A_STAGE;
        const uint32_t bBase = sb + B_BASE + (uint32_t)(c & 3) * B_STAGE;

        // ---- compute chunk c: 4 k16 steps ----
#pragma unroll
        for (int kt = 0; kt < 4; kt++) {
            const uint32_t kx = (uint32_t)kt << 5;
            uint32_t b0[4], b1[4];
            ldmx4(b0, bBase + (bAddr[0] ^ kx));
            ldmx4(b1, bBase + (bAddr[1] ^ kx));
#pragma unroll
            for (int mt = 0; mt < 2; mt++) {
                uint32_t A[4];
#pragma unroll
                for (int j = 0; j < 4; j++) {
                    const uint2 v = *reinterpret_cast<const uint2*>(
                        smem + aOff + rowb[mt * 2 + (j & 1)] + kuo[kt * 2 + (j >> 1)]);
                    A[j] = __byte_perm(v.x, v.y, 0x5410) * 0x3C00u;
                }
                float* am = acc + mt * 16;
                mma16816(am + 0, A, b0[0], b0[1]);
                mma16816(am + 4, A, b0[2], b0[3]);
                mma16816(am + 8, A, b1[0], b1[1]);
                mma16816(am + 12, A, b1[2], b1[3]);
            }
        }
    }

    // ---- epilogue: out = acc + x (fp32 exact self term) ----
#pragma unroll
    for (int mt = 0; mt < 2; mt++) {
        const int r0 = m0 + wm * 32 + mt * 16 + (lane >> 2);
#pragma unroll
        for (int nt = 0; nt < 4; nt++) {
            const int col = wn * 32 + nt * 8 + (lane & 3) * 2;
            const float* ap = acc + mt * 16 + nt * 4;
            float2 xv0 = *(const float2*)(x + (size_t)r0 * DIMF + col);
            *(float2*)(out + (size_t)r0 * DIMF + col) =
                make_float2(ap[0] + xv0.x, ap[1] + xv0.y);
            float2 xv1 = *(const float2*)(x + (size_t)(r0 + 8) * DIMF + col);
            *(float2*)(out + (size_t)(r0 + 8) * DIMF + col) =
                make_float2(ap[2] + xv1.x, ap[3] + xv1.y);
        }
    }
}

extern "C" void kernel_launch(void* const* d_in, const int* in_sizes, int n_in,
                              void* d_out, int out_size) {
    const float* x = (const float*)d_in[0];
    const int* adj = (const int*)d_in[1];
    float* out = (float*)d_out;

    prep_x<<<(NN * DIMF) / 256, 256>>>(x);

    cudaFuncSetAttribute(gp_mma, cudaFuncAttributeMaxDynamicSharedMemorySize,
                         DYN_SMEM);
    gp_mma<<<NN / MT, THREADS, DYN_SMEM>>>(x, adj, out);
}

// round 6
// speedup vs baseline: 2.7181x; 1.0382x over previous
#include <cuda_runtime.h>
#include <cuda_fp16.h>
#include <cstdint>

#define NN      16384
#define DIMF    64
#define GRIDX   296                   // 2 CTAs x 148 SMs, perfectly balanced
#define KC      64                    // K elements per pipeline chunk
#define NC      (NN / KC)             // 256 chunks
#define THREADS 128
#define A_STAGE 16384                 // raw int32 A tile: 64 rows x 256B
#define B_STAGE 8192                  // fp16 B tile: 64 rows x 128B
#define B_BASE  (4 * A_STAGE)         // 65536
#define DYN_SMEM (B_BASE + 4 * B_STAGE)   // 98304

// transposed x in fp16: g_xT[d][j] = (half)x[j][d]
__device__ __half g_xT[DIMF * NN];

// ---------------- helpers ----------------
__device__ __forceinline__ uint32_t smem_u32(const void* p) {
    uint32_t a;
    asm("{ .reg .u64 t; cvta.to.shared.u64 t, %1; cvt.u32.u64 %0, t; }"
        : "=r"(a) : "l"(p));
    return a;
}

__device__ __forceinline__ void ldmx4(uint32_t r[4], uint32_t addr) {
    asm volatile("ldmatrix.sync.aligned.m8n8.x4.shared.b16 {%0,%1,%2,%3}, [%4];"
                 : "=r"(r[0]), "=r"(r[1]), "=r"(r[2]), "=r"(r[3]) : "r"(addr));
}

__device__ __forceinline__ void mma16816(float* c, const uint32_t a[4],
                                         uint32_t b0, uint32_t b1) {
    asm volatile(
        "mma.sync.aligned.m16n8k16.row.col.f32.f16.f16.f32 "
        "{%0,%1,%2,%3}, {%4,%5,%6,%7}, {%8,%9}, {%0,%1,%2,%3};"
        : "+f"(c[0]), "+f"(c[1]), "+f"(c[2]), "+f"(c[3])
        : "r"(a[0]), "r"(a[1]), "r"(a[2]), "r"(a[3]), "r"(b0), "r"(b1));
}

__device__ __forceinline__ void cpa16(uint32_t dst, const void* src) {
    asm volatile("cp.async.cg.shared.global [%0], [%1], 16;"
                 :: "r"(dst), "l"(src) : "memory");
}

// ---------------- pre-pass: x -> transposed fp16 plane ----------------
__global__ void prep_x(const float* __restrict__ x) {
    int id = blockIdx.x * blockDim.x + threadIdx.x;   // 0 .. 64*16384-1
    int d = id >> 14;
    int j = id & (NN - 1);
    g_xT[(size_t)d * NN + j] = __float2half(x[(size_t)j * DIMF + d]);
}

// ---------------- main fused convert + mma.sync GEMM ----------------
__global__ void __launch_bounds__(THREADS, 2)
gp_mma(const float* __restrict__ x, const int* __restrict__ adj,
       float* __restrict__ out) {
    extern __shared__ __align__(1024) char smem[];
    const uint32_t sb = smem_u32(smem);
    const int tid = threadIdx.x;
    const int lane = tid & 31;
    const int wid = tid >> 5;          // 0..3

    // balanced row range for this CTA (55 or 56 real rows inside a 64-row tile)
    const int r_lo = (int)(((long long)blockIdx.x * NN) / GRIDX);
    const int r_hi = (int)(((long long)(blockIdx.x + 1) * NN) / GRIDX);
    const int cnt = r_hi - r_lo;

    // ---- producer A: cp.async of RAW int32, coalesced, row-masked ----
    const int rowp = tid >> 4;          // 0..7
    const int gg = tid & 15;            // 0..15 (16B granules of a 256B row)
    const int* aps = adj + (size_t)(r_lo + rowp) * NN + gg * 4;
    uint32_t adst[8];
    bool amask[8];
#pragma unroll
    for (int i = 0; i < 8; i++) {
        uint32_t row = (uint32_t)(rowp + 8 * i);
        adst[i] = row * 256 + (((uint32_t)gg ^ ((row & 3u) << 1)) << 4);
        amask[i] = (int)row < cnt;
    }

    // ---- producer B: 2 threads/row, 64B (4 granules) each ----
    const int rowB = tid >> 1;          // 0..63
    const int hb = tid & 1;             // 0..1 (64B half of 128B row)
    const __half* bptr = g_xT + (size_t)rowB * NN + hb * 32;
    uint32_t bsw[4];
    {
        uint32_t o0 = (uint32_t)rowB * 128 + (uint32_t)hb * 64;
#pragma unroll
        for (int i = 0; i < 4; i++) {
            uint32_t o = o0 + i * 16;
            bsw[i] = o ^ ((o >> 3) & 0x70);
        }
    }

    // ---- consumer addressing ----
    const int wm = wid >> 1;   // 0..1 : 32-row slice
    const int wn = wid & 1;    // 0..1 : 32-col slice
    const uint32_t xr = (((uint32_t)lane >> 2) & 3u) << 2;
    uint32_t rowb[4];   // [mt*2 + (j&1)] -> row*256
#pragma unroll
    for (int mt = 0; mt < 2; mt++)
#pragma unroll
        for (int jl = 0; jl < 2; jl++)
            rowb[mt * 2 + jl] =
                (uint32_t)(wm * 32 + mt * 16 + (lane >> 2) + jl * 8) * 256;
    uint32_t kuo[8];    // [kt*2 + (j>>1)] -> swizzled unit byte offset
#pragma unroll
    for (int kt = 0; kt < 4; kt++)
#pragma unroll
        for (int jh = 0; jh < 2; jh++)
            kuo[kt * 2 + jh] =
                (((uint32_t)(kt * 8 + (lane & 3) + jh * 4) ^ xr) << 3);

    // B: ldmatrix addressing (swizzled; k-tile advances by XOR of kt<<5)
    uint32_t bAddr[2];
#pragma unroll
    for (int p = 0; p < 2; p++) {
        uint32_t n = (uint32_t)(wn * 32 + p * 16 + (lane & 7) + ((lane >> 4) & 1) * 8);
        uint32_t o = n * 128 + ((((uint32_t)lane >> 3) & 1) << 4);
        bAddr[p] = o ^ ((o >> 3) & 0x70);
    }

    // ---- prologue: chunks 0,1,2 in flight ----
#pragma unroll
    for (int pre = 0; pre < 3; pre++) {
        const uint32_t ad = sb + (uint32_t)(pre & 3) * A_STAGE;
#pragma unroll
        for (int i = 0; i < 8; i++)
            if (amask[i])
                cpa16(ad + adst[i], aps + (size_t)i * (8 * NN) + pre * KC);
        const uint32_t bd = sb + B_BASE + (uint32_t)(pre & 3) * B_STAGE;
#pragma unroll
        for (int i = 0; i < 4; i++)
            cpa16(bd + bsw[i], bptr + pre * KC + i * 8);
        asm volatile("cp.async.commit_group;" ::: "memory");
    }

    float acc[32];
#pragma unroll
    for (int i = 0; i < 32; i++) acc[i] = 0.f;

    for (int c = 0; c < NC; c++) {
        // own groups: <=2 pending -> group c complete
        asm volatile("cp.async.wait_group 2;" ::: "memory");
        __syncthreads();   // group-c data visible to all; WAR for stage (c+3)&3

        // issue chunk c+3 into stage (c+3)&3 (== (c-1)&3, last read at c-1)
        if (c + 3 < NC) {
            const uint32_t ad = sb + (uint32_t)((c + 3) & 3) * A_STAGE;
#pragma unroll
            for (int i = 0; i < 8; i++)
                if (amask[i])
                    cpa16(ad + adst[i], aps + (size_t)i * (8 * NN) + (c + 3) * KC);
            const uint32_t bd = sb + B_BASE + (uint32_t)((c + 3) & 3) * B_STAGE;
#pragma unroll
            for (int i = 0; i < 4; i++)
                cpa16(bd + bsw[i], bptr + (size_t)(c + 3) * KC + i * 8);
        }
        asm volatile("cp.async.commit_group;" ::: "memory");

        const uint32_t aOff = (uint32_t)(c & 3) * A_STAGE;
        const uint32_t bBase = sb + B_BASE + (uint32_t)(c & 3) * B_STAGE;

        // ---- compute chunk c: 4 k16 steps ----
#pragma unroll
        for (int kt = 0; kt < 4; kt++) {
            const uint32_t kx = (uint32_t)kt << 5;
            uint32_t b0[4], b1[4];
            ldmx4(b0, bBase + (bAddr[0] ^ kx));
            ldmx4(b1, bBase + (bAddr[1] ^ kx));
#pragma unroll
            for (int mt = 0; mt < 2; mt++) {
                uint32_t A[4];
#pragma unroll
                for (int j = 0; j < 4; j++) {
                    const uint2 v = *reinterpret_cast<const uint2*>(
                        smem + aOff + rowb[mt * 2 + (j & 1)] + kuo[kt * 2 + (j >> 1)]);
                    A[j] = __byte_perm(v.x, v.y, 0x5410) * 0x3C00u;
                }
                float* am = acc + mt * 16;
                mma16816(am + 0, A, b0[0], b0[1]);
                mma16816(am + 4, A, b0[2], b0[3]);
                mma16816(am + 8, A, b1[0], b1[1]);
                mma16816(am + 12, A, b1[2], b1[3]);
            }
        }
    }

    // ---- epilogue: out = acc + x (fp32 exact self term), masked rows ----
#pragma unroll
    for (int mt = 0; mt < 2; mt++) {
        const int rloc = wm * 32 + mt * 16 + (lane >> 2);
#pragma unroll
        for (int nt = 0; nt < 4; nt++) {
            const int col = wn * 32 + nt * 8 + (lane & 3) * 2;
            const float* ap = acc + mt * 16 + nt * 4;
            if (rloc < cnt) {
                const int r0 = r_lo + rloc;
                float2 xv0 = *(const float2*)(x + (size_t)r0 * DIMF + col);
                *(float2*)(out + (size_t)r0 * DIMF + col) =
                    make_float2(ap[0] + xv0.x, ap[1] + xv0.y);
            }
            if (rloc + 8 < cnt) {
                const int r1 = r_lo + rloc + 8;
                float2 xv1 = *(const float2*)(x + (size_t)r1 * DIMF + col);
                *(float2*)(out + (size_t)r1 * DIMF + col) =
                    make_float2(ap[2] + xv1.x, ap[3] + xv1.y);
            }
        }
    }
}

extern "C" void kernel_launch(void* const* d_in, const int* in_sizes, int n_in,
                              void* d_out, int out_size) {
    const float* x = (const float*)d_in[0];
    const int* adj = (const int*)d_in[1];
    float* out = (float*)d_out;

    prep_x<<<(NN * DIMF) / 256, 256>>>(x);

    cudaFuncSetAttribute(gp_mma, cudaFuncAttributeMaxDynamicSharedMemorySize,
                         DYN_SMEM);
    gp_mma<<<GRIDX, THREADS, DYN_SMEM>>>(x, adj, out);
}